// round 7
// baseline (speedup 1.0000x reference)
#include <cuda_runtime.h>
#include <cstdint>

// out[e, 0:128] = node_states[src[e], :] ; out[e, 128:256] = node_states[tgt[e], :]
// Binder experiment: every prior variant (49.6-51.6us) pushed both the 328 MB
// load stream AND the 328 MB store stream through L1tex (consistently the
// top-ranked unit at 73-76%). This version stages the output tile in SMEM and
// writes it with one cp.async.bulk (16 KB) per CTA — the TMA store path
// bypasses L1tex entirely, halving its wavefront traffic.
// 8 warps x 2 edges = 16 edges/CTA -> 16 KB output tile.

#define EDGES_PER_CTA 16

__global__ __launch_bounds__(256) void node_propagate_tma(
    const float4* __restrict__ ns,   // [N_NODES, 32] as float4
    const int* __restrict__ src,     // [E] int32
    const int* __restrict__ tgt,     // [E] int32
    float4* __restrict__ out,        // [E, 64] as float4
    int E)
{
    __shared__ __align__(128) float4 buf[EDGES_PER_CTA * 64];  // 16 KB

    const int tile = blockIdx.x;
    const int wid  = threadIdx.x >> 5;
    const int lane = threadIdx.x & 31;
    const int e0   = tile * EDGES_PER_CTA + wid * 2;

    if ((tile + 1) * EDGES_PER_CTA <= E) {
        // ---- Fast path: full tile (always taken for E=320000) ----
        const int2 s2 = *(const int2*)(src + e0);
        const int2 t2 = *(const int2*)(tgt + e0);

        // 4 independent gathers in flight (node_states 5.12 MB, L2-resident).
        const float4 a0 = __ldg(&ns[(size_t)s2.x * 32 + lane]);
        const float4 b0 = __ldg(&ns[(size_t)t2.x * 32 + lane]);
        const float4 a1 = __ldg(&ns[(size_t)s2.y * 32 + lane]);
        const float4 b1 = __ldg(&ns[(size_t)t2.y * 32 + lane]);

        // Stage tile in SMEM (contiguous, conflict-free 16B stores).
        float4* b = buf + (size_t)(wid * 2) * 64;
        b[lane]       = a0;
        b[32 + lane]  = b0;
        b[64 + lane]  = a1;
        b[96 + lane]  = b1;
        __syncthreads();

        // One bulk store SMEM -> GMEM; bypasses L1tex, full-line writes.
        if (threadIdx.x == 0) {
            asm volatile("fence.proxy.async.shared::cta;" ::: "memory");
            uint32_t saddr;
            asm("{ .reg .u64 t; cvta.to.shared.u64 t, %1; cvt.u32.u64 %0, t; }"
                : "=r"(saddr) : "l"(buf));
            const float4* dst = out + (size_t)tile * EDGES_PER_CTA * 64;
            asm volatile(
                "cp.async.bulk.global.shared::cta.bulk_group [%0], [%1], %2;"
                :: "l"(dst), "r"(saddr), "n"(EDGES_PER_CTA * 64 * 16)
                : "memory");
            asm volatile("cp.async.bulk.commit_group;" ::: "memory");
            asm volatile("cp.async.bulk.wait_group 0;" ::: "memory");
        }
    } else {
        // ---- Tail: per-edge direct stores (unused for E=320000) ----
        for (int e = e0; e < E && e < e0 + 2; e++) {
            const int s = __ldg(&src[e]);
            const int t = __ldg(&tgt[e]);
            const float4 a = __ldg(&ns[(size_t)s * 32 + lane]);
            const float4 bb = __ldg(&ns[(size_t)t * 32 + lane]);
            float4* o = out + (size_t)e * 64;
            __stcs(o + lane,      a);
            __stcs(o + 32 + lane, bb);
        }
    }
}

extern "C" void kernel_launch(void* const* d_in, const int* in_sizes, int n_in,
                              void* d_out, int out_size)
{
    const float4* ns  = (const float4*)d_in[0];
    const int*    src = (const int*)d_in[1];
    const int*    tgt = (const int*)d_in[2];
    float4*       out = (float4*)d_out;

    const int E      = in_sizes[1];              // 320000 edges
    const int blocks = (E + EDGES_PER_CTA - 1) / EDGES_PER_CTA;  // 20000

    node_propagate_tma<<<blocks, 256>>>(ns, src, tgt, out, E);
}